// round 3
// baseline (speedup 1.0000x reference)
#include <cuda_runtime.h>
#include <math.h>
#include <limits.h>

// Problem shape (fixed by reference setup_inputs)
#define BB_B 32
#define BB_H 512
#define BB_W 512
#define BB_HW (BB_H * BB_W)
#define BB_C 21
#define PPB  256                 // pixels per staging tile
#define TILE_F (PPB * BB_C)      // 5376 floats per tile
#define TILE_V4 (TILE_F / 4)     // 1344 float4
#define ROWS_PB 8                // rows per main-kernel block
#define NEGF (-3.402823466e38f)

// Scratch: 8 groups x 32 batches of int box coords.
// groups: 0 p_ymin 1 p_xmin 2 p_ymax 3 p_xmax 4 t_ymin 5 t_xmin 6 t_ymax 7 t_xmax
// Statically initialized; bb_finalize_kernel restores this state every call,
// so each kernel_launch (and each graph replay) starts from identical scratch.
#define R8MAX INT_MAX,INT_MAX,INT_MAX,INT_MAX,INT_MAX,INT_MAX,INT_MAX,INT_MAX
#define R8MIN INT_MIN,INT_MIN,INT_MIN,INT_MIN,INT_MIN,INT_MIN,INT_MIN,INT_MIN
#define R32MAX R8MAX,R8MAX,R8MAX,R8MAX
#define R32MIN R8MIN,R8MIN,R8MIN,R8MIN
__device__ int g_boxes[8 * BB_B] = {
    R32MAX, R32MAX, R32MIN, R32MIN,   // pred
    R32MAX, R32MAX, R32MIN, R32MIN    // true
};

// ---------------------------------------------------------------------------
// Probe: seed scratch boxes from border rows {0,511} and columns {0,511}.
// Sound for any input (updates only from genuinely masked pixels). For
// uniform-random data this establishes the full [0,0,511,511] box.
// Grid: (16, B). seg 0..7 = row tiles, seg 8..15 = column row-bands.
// ---------------------------------------------------------------------------
__global__ __launch_bounds__(256) void bb_probe_kernel(
    const float* __restrict__ pred,
    const float* __restrict__ tru)
{
    __shared__ float tile[TILE_F];
    __shared__ unsigned s_ball[PPB / 32];

    const int b    = blockIdx.y;
    const int seg  = blockIdx.x;
    const int tid  = threadIdx.x;
    const int lane = tid & 31;
    const int warp = tid >> 5;

    if (seg < 8) {
        // ----- row tile: tensor=seg&1, y=0|511, half=(seg>>2)&1 -----
        const float* src = (seg & 1) ? tru : pred;
        const int off = (seg & 1) ? 4 * BB_B : 0;
        const int y   = ((seg >> 1) & 1) ? (BB_H - 1) : 0;
        const int x0  = ((seg >> 2) & 1) * PPB;

        const size_t base = ((size_t)b * BB_HW + (size_t)y * BB_W + x0) * BB_C;
        const float4* g = (const float4*)(src + base);
        float4* s4 = (float4*)tile;
        #pragma unroll
        for (int i = 0; i < 6; ++i) {
            int idx = tid + i * PPB;
            if (idx < TILE_V4) s4[idx] = g[idx];
        }
        __syncthreads();
        const float* row = tile + tid * BB_C;   // stride 21: conflict-free
        float p0 = row[0];
        float mx = row[1];
        #pragma unroll
        for (int c = 2; c < BB_C; ++c) mx = fmaxf(mx, row[c]);
        unsigned bl = __ballot_sync(0xffffffffu, mx > p0);
        if (lane == 0) s_ball[warp] = bl;
        __syncthreads();
        if (tid == 0) {
            int xmn = INT_MAX, xmx = INT_MIN;
            bool any = false;
            #pragma unroll
            for (int w = 0; w < PPB / 32; ++w) {
                unsigned wb = s_ball[w];
                if (wb) {
                    any = true;
                    xmn = min(xmn, w * 32 + (__ffs(wb) - 1));
                    xmx = max(xmx, w * 32 + (31 - __clz(wb)));
                }
            }
            if (any) {
                atomicMin(&g_boxes[off + 0 * BB_B + b], y);
                atomicMin(&g_boxes[off + 1 * BB_B + b], x0 + xmn);
                atomicMax(&g_boxes[off + 2 * BB_B + b], y);
                atomicMax(&g_boxes[off + 3 * BB_B + b], x0 + xmx);
            }
        }
    } else {
        // ----- column band: thread-per-row, 21 independent LDGs (MLP=21) -----
        const int s = seg - 8;
        const float* src = (s & 1) ? tru : pred;
        const int off = (s & 1) ? 4 * BB_B : 0;
        const int x   = ((s >> 1) & 1) ? (BB_W - 1) : 0;
        const int y   = ((s >> 2) & 1) * 256 + tid;   // each thread: one row

        const float* p = src + ((size_t)b * BB_HW + (size_t)y * BB_W + x) * BB_C;
        float v[BB_C];
        #pragma unroll
        for (int c = 0; c < BB_C; ++c) v[c] = __ldg(p + c);
        float mx = v[1];
        #pragma unroll
        for (int c = 2; c < BB_C; ++c) mx = fmaxf(mx, v[c]);
        unsigned bl = __ballot_sync(0xffffffffu, mx > v[0]);
        if (lane == 0 && bl) {
            const int ybase = y - lane;   // lane==0 -> y is warp's first row
            atomicMin(&g_boxes[off + 0 * BB_B + b], ybase + (__ffs(bl) - 1));
            atomicMin(&g_boxes[off + 1 * BB_B + b], x);
            atomicMax(&g_boxes[off + 2 * BB_B + b], ybase + (31 - __clz(bl)));
            atomicMax(&g_boxes[off + 3 * BB_B + b], x);
        }
    }
}

// ---------------------------------------------------------------------------
// Main: each block owns ROWS_PB full rows of one batch. Skips entirely when
// its band provably cannot improve either tensor's current box.
// ---------------------------------------------------------------------------
__global__ __launch_bounds__(PPB) void bb_main_kernel(
    const float* __restrict__ pred,
    const float* __restrict__ tru)
{
    __shared__ float tile[TILE_F];
    __shared__ unsigned s_ball[2][PPB / 32];
    __shared__ int s_box[8];

    const int b  = blockIdx.y;
    const int y0 = blockIdx.x * ROWS_PB;
    const int tid  = threadIdx.x;
    const int lane = tid & 31;
    const int warp = tid >> 5;

    if (tid < 8) s_box[tid] = g_boxes[tid * BB_B + b];
    __syncthreads();
    {
        const int y1 = y0 + ROWS_PB - 1;
        bool sp = (s_box[0] <= y0) && (s_box[2] >= y1) &&
                  (s_box[1] <= 0)  && (s_box[3] >= BB_W - 1);
        bool st = (s_box[4] <= y0) && (s_box[6] >= y1) &&
                  (s_box[5] <= 0)  && (s_box[7] >= BB_W - 1);
        if (sp && st) return;       // uniform across the block
    }

    // Fallback streaming path (runs only when the box can still grow).
    int e[2][4] = {{INT_MAX, INT_MAX, INT_MIN, INT_MIN},
                   {INT_MAX, INT_MAX, INT_MIN, INT_MIN}};   // thread 0 only

    for (int r = 0; r < ROWS_PB; ++r) {
        const int y = y0 + r;
        for (int hx = 0; hx < 2; ++hx) {
            const size_t base = ((size_t)b * BB_HW + (size_t)y * BB_W + hx * PPB) * BB_C;
            bool m[2];
            #pragma unroll
            for (int pass = 0; pass < 2; ++pass) {
                const float4* g = (const float4*)((pass ? tru : pred) + base);
                float4* s4 = (float4*)tile;
                __syncthreads();
                #pragma unroll
                for (int i = 0; i < 6; ++i) {
                    int idx = tid + i * PPB;
                    if (idx < TILE_V4) s4[idx] = g[idx];
                }
                __syncthreads();
                const float* row = tile + tid * BB_C;
                float p0 = row[0];
                float mx = row[1];
                #pragma unroll
                for (int c = 2; c < BB_C; ++c) mx = fmaxf(mx, row[c]);
                m[pass] = mx > p0;
            }
            unsigned b0 = __ballot_sync(0xffffffffu, m[0]);
            unsigned b1 = __ballot_sync(0xffffffffu, m[1]);
            if (lane == 0) { s_ball[0][warp] = b0; s_ball[1][warp] = b1; }
            __syncthreads();
            if (tid == 0) {
                #pragma unroll
                for (int t = 0; t < 2; ++t) {
                    int mn = INT_MAX, mx = INT_MIN;
                    bool any = false;
                    #pragma unroll
                    for (int w = 0; w < PPB / 32; ++w) {
                        unsigned bl = s_ball[t][w];
                        if (bl) {
                            any = true;
                            mn = min(mn, w * 32 + (__ffs(bl) - 1));
                            mx = max(mx, w * 32 + (31 - __clz(bl)));
                        }
                    }
                    if (any) {
                        e[t][0] = min(e[t][0], y);
                        e[t][1] = min(e[t][1], hx * PPB + mn);
                        e[t][2] = max(e[t][2], y);
                        e[t][3] = max(e[t][3], hx * PPB + mx);
                    }
                }
            }
            __syncthreads();
        }
    }
    if (tid == 0) {
        #pragma unroll
        for (int t = 0; t < 2; ++t) {
            if (e[t][0] != INT_MAX) {
                int off = t * 4 * BB_B;
                atomicMin(&g_boxes[off + 0 * BB_B + b], e[t][0]);
                atomicMin(&g_boxes[off + 1 * BB_B + b], e[t][1]);
                atomicMax(&g_boxes[off + 2 * BB_B + b], e[t][2]);
                atomicMax(&g_boxes[off + 3 * BB_B + b], e[t][3]);
            }
        }
    }
}

__device__ __forceinline__ float bb_sq(float v) { return v * v; }

// Computes the final scalar AND resets the scratch to its initial state so the
// next call (graph replay) starts clean.
__global__ void bb_finalize_kernel(float* out) {
    const int tid = threadIdx.x;     // 256 threads
    float pen = 0.0f;
    if (tid < BB_B) {
        const int b = tid;
        int pym = g_boxes[0 * BB_B + b], pxm = g_boxes[1 * BB_B + b];
        int pyM = g_boxes[2 * BB_B + b], pxM = g_boxes[3 * BB_B + b];
        int tym = g_boxes[4 * BB_B + b], txm = g_boxes[5 * BB_B + b];
        int tyM = g_boxes[6 * BB_B + b], txM = g_boxes[7 * BB_B + b];
        bool hp = (pym != INT_MAX);
        bool ht = (tym != INT_MAX);

        float py0, px0, py1, px1, ty0, tx0, ty1, tx1;
        if (hp) { py0 = (float)pym; px0 = (float)pxm; py1 = (float)pyM; px1 = (float)pxM; }
        else    { py0 = 0.f; px0 = 0.f; py1 = 1.f; px1 = 1.f; }
        if (ht) { ty0 = (float)tym; tx0 = (float)txm; ty1 = (float)tyM; tx1 = (float)txM; }
        else    { ty0 = 0.f; tx0 = 0.f; ty1 = 1.f; tx1 = 1.f; }

        float pa = (py1 - py0 + 1.f) * (px1 - px0 + 1.f);
        float ta = (ty1 - ty0 + 1.f) * (tx1 - tx0 + 1.f);
        float area_pen = fmaxf(pa - ta, 0.f) / (ta + 1.f);

        float co = sqrtf(bb_sq((py0 + py1) * 0.5f - (ty0 + ty1) * 0.5f) +
                         bb_sq((px0 + px1) * 0.5f - (tx0 + tx1) * 0.5f)) / 20.f;

        float iy0 = fmaxf(py0, ty0), ix0 = fmaxf(px0, tx0);
        float iy1 = fminf(py1, ty1), ix1 = fminf(px1, tx1);
        float ia  = fmaxf(0.f, iy1 - iy0 + 1.f) * fmaxf(0.f, ix1 - ix0 + 1.f);
        float ua  = pa + ta - ia + 1e-6f;
        float iou_pen = 1.f - ia / ua;

        pen = (hp && ht) ? tanhf(area_pen + co + iou_pen) : 0.f;
    }
    __syncthreads();                 // all reads done before reset
    {
        int grp = tid >> 5;
        bool isMin = (grp == 0 || grp == 1 || grp == 4 || grp == 5);
        g_boxes[tid] = isMin ? INT_MAX : INT_MIN;
    }
    if (tid < 32) {
        #pragma unroll
        for (int o = 16; o > 0; o >>= 1)
            pen += __shfl_down_sync(0xffffffffu, pen, o);
        if (tid == 0) out[0] = 0.05f * (pen / (float)BB_B);
    }
}

extern "C" void kernel_launch(void* const* d_in, const int* in_sizes, int n_in,
                              void* d_out, int out_size)
{
    const float* pred = (const float*)d_in[0];   // prediction_probs [32,512,512,21]
    const float* tru  = (const float*)d_in[1];   // expected_onehot  [32,512,512,21]
    float* out = (float*)d_out;

    dim3 pgrid(16, BB_B);                        // 512 probe blocks, 1 tile each
    bb_probe_kernel<<<pgrid, 256>>>(pred, tru);

    dim3 mgrid(BB_H / ROWS_PB, BB_B);            // (64, 32) = 2048 blocks
    bb_main_kernel<<<mgrid, PPB>>>(pred, tru);

    bb_finalize_kernel<<<1, 256>>>(out);
}

// round 4
// speedup vs baseline: 1.9359x; 1.9359x over previous
#include <cuda_runtime.h>
#include <math.h>
#include <limits.h>

// Problem shape (fixed by reference setup_inputs)
#define BB_B 32
#define BB_H 512
#define BB_W 512
#define BB_HW (BB_H * BB_W)
#define BB_C 21
#define PPB  256                 // threads / staging tile pixels per block
#define TILE_F (PPB * BB_C)      // 5376 floats per tile
#define TILE_V4 (TILE_F / 4)     // 1344 float4
#define ROWS_PB 16               // rows per main-kernel block
#define NBLK (BB_B * (BB_H / ROWS_PB))   // 1024 main blocks

// Scratch: 8 groups x 32 batches of int box coords.
// groups: 0 p_ymin 1 p_xmin 2 p_ymax 3 p_xmax 4 t_ymin 5 t_xmin 6 t_ymax 7 t_xmax
// Statically initialized; the last main block restores this state every call,
// so each kernel_launch (and each graph replay) starts from identical scratch.
#define R8MAX INT_MAX,INT_MAX,INT_MAX,INT_MAX,INT_MAX,INT_MAX,INT_MAX,INT_MAX
#define R8MIN INT_MIN,INT_MIN,INT_MIN,INT_MIN,INT_MIN,INT_MIN,INT_MIN,INT_MIN
#define R32MAX R8MAX,R8MAX,R8MAX,R8MAX
#define R32MIN R8MIN,R8MIN,R8MIN,R8MIN
__device__ int g_boxes[8 * BB_B] = {
    R32MAX, R32MAX, R32MIN, R32MIN,   // pred
    R32MAX, R32MAX, R32MIN, R32MIN    // true
};
__device__ unsigned g_done = 0;

// ---------------------------------------------------------------------------
// Probe: one warp per (border line, tensor, batch); each lane tests ONE pixel
// (32 pixels per line). A single masked pixel on each of the 4 border lines
// is enough to make the skip predicate true for every band. Updates come only
// from genuinely masked pixels -> sound for any input.
// Grid: (BB_B), block 256 = 8 warps = 4 lines x 2 tensors.
// ---------------------------------------------------------------------------
__global__ __launch_bounds__(256) void bb_probe_kernel(
    const float* __restrict__ pred,
    const float* __restrict__ tru)
{
    const int b    = blockIdx.x;
    const int warp = threadIdx.x >> 5;
    const int lane = threadIdx.x & 31;
    const int line = warp & 3;                 // 0:y=0 1:y=511 2:x=0 3:x=511
    const float* src = (warp & 4) ? tru : pred;
    const int off = (warp & 4) ? 4 * BB_B : 0;

    int y, x;
    if      (line == 0) { y = 0;        x = lane; }
    else if (line == 1) { y = BB_H - 1; x = lane; }
    else if (line == 2) { x = 0;        y = lane; }
    else                { x = BB_W - 1; y = lane; }

    const float* p = src + ((size_t)b * BB_HW + (size_t)y * BB_W + x) * BB_C;
    float v0 = __ldg(p);
    float mx = __ldg(p + 1);
    #pragma unroll
    for (int c = 2; c < BB_C; ++c) mx = fmaxf(mx, __ldg(p + c));

    unsigned bl = __ballot_sync(0xffffffffu, mx > v0);
    if (lane == 0 && bl) {
        int lo = __ffs(bl) - 1, hi = 31 - __clz(bl);
        int ymn, xmn, ymx, xmx;
        if (line < 2) { ymn = y;  ymx = y;  xmn = lo; xmx = hi; }
        else          { xmn = x;  xmx = x;  ymn = lo; ymx = hi; }
        atomicMin(&g_boxes[off + 0 * BB_B + b], ymn);
        atomicMin(&g_boxes[off + 1 * BB_B + b], xmn);
        atomicMax(&g_boxes[off + 2 * BB_B + b], ymx);
        atomicMax(&g_boxes[off + 3 * BB_B + b], xmx);
    }
}

__device__ __forceinline__ float bb_sq(float v) { return v * v; }

// ---------------------------------------------------------------------------
// Main: each block owns ROWS_PB full rows of one batch. Skips the streaming
// work when its band provably cannot improve either tensor's current box.
// The LAST block to finish computes the final scalar and resets the scratch
// (fused finalize: one fewer kernel launch).
// ---------------------------------------------------------------------------
__global__ __launch_bounds__(PPB) void bb_main_kernel(
    const float* __restrict__ pred,
    const float* __restrict__ tru,
    float* __restrict__ out)
{
    __shared__ float tile[TILE_F];
    __shared__ unsigned s_ball[2][PPB / 32];
    __shared__ int s_box[8];
    __shared__ int s_last;

    const int b  = blockIdx.y;
    const int y0 = blockIdx.x * ROWS_PB;
    const int tid  = threadIdx.x;
    const int lane = tid & 31;
    const int warp = tid >> 5;

    if (tid < 8) s_box[tid] = g_boxes[tid * BB_B + b];
    __syncthreads();
    bool skip;
    {
        const int y1 = y0 + ROWS_PB - 1;
        bool sp = (s_box[0] <= y0) && (s_box[2] >= y1) &&
                  (s_box[1] <= 0)  && (s_box[3] >= BB_W - 1);
        bool st = (s_box[4] <= y0) && (s_box[6] >= y1) &&
                  (s_box[5] <= 0)  && (s_box[7] >= BB_W - 1);
        skip = sp && st;            // uniform across the block
    }

    if (!skip) {
        // Fallback streaming path (runs only when the box can still grow).
        int e[2][4] = {{INT_MAX, INT_MAX, INT_MIN, INT_MIN},
                       {INT_MAX, INT_MAX, INT_MIN, INT_MIN}};  // thread 0 only

        for (int r = 0; r < ROWS_PB; ++r) {
            const int y = y0 + r;
            for (int hx = 0; hx < 2; ++hx) {
                const size_t base = ((size_t)b * BB_HW + (size_t)y * BB_W + hx * PPB) * BB_C;
                bool m[2];
                #pragma unroll
                for (int pass = 0; pass < 2; ++pass) {
                    const float4* g = (const float4*)((pass ? tru : pred) + base);
                    float4* s4 = (float4*)tile;
                    __syncthreads();
                    #pragma unroll
                    for (int i = 0; i < 6; ++i) {
                        int idx = tid + i * PPB;
                        if (idx < TILE_V4) s4[idx] = g[idx];
                    }
                    __syncthreads();
                    const float* row = tile + tid * BB_C;
                    float p0 = row[0];
                    float mx = row[1];
                    #pragma unroll
                    for (int c = 2; c < BB_C; ++c) mx = fmaxf(mx, row[c]);
                    m[pass] = mx > p0;
                }
                unsigned b0 = __ballot_sync(0xffffffffu, m[0]);
                unsigned b1 = __ballot_sync(0xffffffffu, m[1]);
                if (lane == 0) { s_ball[0][warp] = b0; s_ball[1][warp] = b1; }
                __syncthreads();
                if (tid == 0) {
                    #pragma unroll
                    for (int t = 0; t < 2; ++t) {
                        int mn = INT_MAX, mx = INT_MIN;
                        bool any = false;
                        #pragma unroll
                        for (int w = 0; w < PPB / 32; ++w) {
                            unsigned bl = s_ball[t][w];
                            if (bl) {
                                any = true;
                                mn = min(mn, w * 32 + (__ffs(bl) - 1));
                                mx = max(mx, w * 32 + (31 - __clz(bl)));
                            }
                        }
                        if (any) {
                            e[t][0] = min(e[t][0], y);
                            e[t][1] = min(e[t][1], hx * PPB + mn);
                            e[t][2] = max(e[t][2], y);
                            e[t][3] = max(e[t][3], hx * PPB + mx);
                        }
                    }
                }
                __syncthreads();
            }
        }
        if (tid == 0) {
            #pragma unroll
            for (int t = 0; t < 2; ++t) {
                if (e[t][0] != INT_MAX) {
                    int off = t * 4 * BB_B;
                    atomicMin(&g_boxes[off + 0 * BB_B + b], e[t][0]);
                    atomicMin(&g_boxes[off + 1 * BB_B + b], e[t][1]);
                    atomicMax(&g_boxes[off + 2 * BB_B + b], e[t][2]);
                    atomicMax(&g_boxes[off + 3 * BB_B + b], e[t][3]);
                }
            }
        }
    }

    // ---- completion protocol: last finished block runs the finalize ----
    if (tid == 0) {
        __threadfence();                           // publish this block's atomics
        unsigned r = atomicAdd(&g_done, 1u);
        s_last = (r == NBLK - 1) ? 1 : 0;
    }
    __syncthreads();
    if (!s_last) return;
    __threadfence();                               // acquire: see all blocks' writes

    float pen = 0.0f;
    if (tid < BB_B) {
        const int bb = tid;
        int pym = g_boxes[0 * BB_B + bb], pxm = g_boxes[1 * BB_B + bb];
        int pyM = g_boxes[2 * BB_B + bb], pxM = g_boxes[3 * BB_B + bb];
        int tym = g_boxes[4 * BB_B + bb], txm = g_boxes[5 * BB_B + bb];
        int tyM = g_boxes[6 * BB_B + bb], txM = g_boxes[7 * BB_B + bb];
        bool hp = (pym != INT_MAX);
        bool ht = (tym != INT_MAX);

        float py0, px0, py1, px1, ty0, tx0, ty1, tx1;
        if (hp) { py0 = (float)pym; px0 = (float)pxm; py1 = (float)pyM; px1 = (float)pxM; }
        else    { py0 = 0.f; px0 = 0.f; py1 = 1.f; px1 = 1.f; }
        if (ht) { ty0 = (float)tym; tx0 = (float)txm; ty1 = (float)tyM; tx1 = (float)txM; }
        else    { ty0 = 0.f; tx0 = 0.f; ty1 = 1.f; tx1 = 1.f; }

        float pa = (py1 - py0 + 1.f) * (px1 - px0 + 1.f);
        float ta = (ty1 - ty0 + 1.f) * (tx1 - tx0 + 1.f);
        float area_pen = fmaxf(pa - ta, 0.f) / (ta + 1.f);

        float co = sqrtf(bb_sq((py0 + py1) * 0.5f - (ty0 + ty1) * 0.5f) +
                         bb_sq((px0 + px1) * 0.5f - (tx0 + tx1) * 0.5f)) / 20.f;

        float iy0 = fmaxf(py0, ty0), ix0 = fmaxf(px0, tx0);
        float iy1 = fminf(py1, ty1), ix1 = fminf(px1, tx1);
        float ia  = fmaxf(0.f, iy1 - iy0 + 1.f) * fmaxf(0.f, ix1 - ix0 + 1.f);
        float ua  = pa + ta - ia + 1e-6f;
        float iou_pen = 1.f - ia / ua;

        pen = (hp && ht) ? tanhf(area_pen + co + iou_pen) : 0.f;
    }
    __syncthreads();               // all g_boxes reads done before the reset
    {
        // reset scratch + counter for the next graph replay
        int grp = tid >> 5;
        bool isMin = (grp == 0 || grp == 1 || grp == 4 || grp == 5);
        g_boxes[tid] = isMin ? INT_MAX : INT_MIN;
        if (tid == 0) g_done = 0;
    }
    if (tid < 32) {
        #pragma unroll
        for (int o = 16; o > 0; o >>= 1)
            pen += __shfl_down_sync(0xffffffffu, pen, o);
        if (tid == 0) out[0] = 0.05f * (pen / (float)BB_B);
    }
}

extern "C" void kernel_launch(void* const* d_in, const int* in_sizes, int n_in,
                              void* d_out, int out_size)
{
    const float* pred = (const float*)d_in[0];   // prediction_probs [32,512,512,21]
    const float* tru  = (const float*)d_in[1];   // expected_onehot  [32,512,512,21]
    float* out = (float*)d_out;

    bb_probe_kernel<<<BB_B, 256>>>(pred, tru);   // 32 blocks, 688 KB total read

    dim3 mgrid(BB_H / ROWS_PB, BB_B);            // (32, 32) = 1024 blocks
    bb_main_kernel<<<mgrid, PPB>>>(pred, tru, out);
}